// round 4
// baseline (speedup 1.0000x reference)
#include <cuda_runtime.h>

#define NB 64
#define CC 512
#define LL 256
#define EPSF 1e-12f
#define NT (CC/64)            // 8 row tiles of 64
#define NPAIR (NT*(NT+1)/2)   // 36 upper-triangular tile pairs

// -------- scratch (static device globals: allocation-free rule) ----------
__device__ float g_es[NB*CC*LL];     // compacted student rows
__device__ float g_et[NB*CC*LL];     // compacted teacher rows
__device__ float g_sq_s[NB*CC];      // squared norms (compacted)
__device__ float g_sq_t[NB*CC];
__device__ int   g_npos[NB];
__device__ float g_sum_s[NB];        // sum of offdiag distances
__device__ float g_sum_t[NB];
__device__ float g_Ds[NB*CC*CC];     // distance matrices (upper tiles valid)
__device__ float g_Dt[NB*CC*CC];

// ======================= kernel 1: compact + norms =======================
__global__ void k_compact(const float* __restrict__ s,
                          const float* __restrict__ t,
                          const int* __restrict__ targ,
                          float* __restrict__ out) {
    int n   = blockIdx.x;
    int tid = threadIdx.x;            // 512 threads
    int lane = tid & 31, wid = tid >> 5;

    __shared__ int sh_idx[CC];
    __shared__ int sh_wsum[16];
    __shared__ int sh_P;

    int m = (targ[n*CC + tid] != 0);
    unsigned bal = __ballot_sync(0xffffffffu, m);
    int wpre = __popc(bal & ((1u << lane) - 1u));
    if (lane == 0) sh_wsum[wid] = __popc(bal);
    __syncthreads();
    if (tid == 0) {
        int acc = 0;
        #pragma unroll
        for (int w = 0; w < 16; w++) { int v = sh_wsum[w]; sh_wsum[w] = acc; acc += v; }
        sh_P = acc;
        g_npos[n]  = acc;
        g_sum_s[n] = 0.f;
        g_sum_t[n] = 0.f;
        if (n == 0) out[0] = 0.f;     // d_out is poisoned; zero before K3's atomics
    }
    __syncthreads();
    int P = sh_P;
    if (m) sh_idx[sh_wsum[wid] + wpre] = tid;
    __syncthreads();

    const float* sbase = s + (long long)n*CC*LL;
    const float* tbase = t + (long long)n*CC*LL;
    float* des = g_es + (long long)n*CC*LL;
    float* det = g_et + (long long)n*CC*LL;

    for (int e = tid; e < P*LL; e += blockDim.x) {
        int r = e >> 8, col = e & (LL - 1);
        int src = sh_idx[r];
        des[e] = sbase[src*LL + col];
        det[e] = tbase[src*LL + col];
    }
    __syncthreads();

    // squared norms: one warp per compacted row
    for (int r = wid; r < P; r += 16) {
        const float* rs = des + r*LL;
        const float* rt = det + r*LL;
        float a = 0.f, b = 0.f;
        for (int c = lane; c < LL; c += 32) {
            float v = rs[c]; a += v*v;
            float w = rt[c]; b += w*w;
        }
        #pragma unroll
        for (int off = 16; off; off >>= 1) {
            a += __shfl_down_sync(0xffffffffu, a, off);
            b += __shfl_down_sync(0xffffffffu, b, off);
        }
        if (lane == 0) { g_sq_s[n*CC + r] = a; g_sq_t[n*CC + r] = b; }
    }
}

// ============ kernel 2: Gram -> distances (upper tiles) + sums ============
// block = 256 threads, computes a 64x64 tile, 4x4 register micro-tile
__global__ void k_dist() {
    int n     = blockIdx.z;
    int which = blockIdx.y;   // 0 = student, 1 = teacher

    const float* E  = which ? (g_et   + (long long)n*CC*LL) : (g_es   + (long long)n*CC*LL);
    const float* SQ = which ? (g_sq_t + n*CC)               : (g_sq_s + n*CC);
    float*       D  = which ? (g_Dt   + (long long)n*CC*CC) : (g_Ds   + (long long)n*CC*CC);
    float*       SM = which ? (g_sum_t + n)                 : (g_sum_s + n);

    int P = g_npos[n];

    // decode upper-triangular tile pair (bi <= bj)
    int tlin = blockIdx.x, bi = 0, rem = NT;
    while (tlin >= rem) { tlin -= rem; bi++; rem--; }
    int bj = bi + tlin;
    int i0 = bi * 64, j0 = bj * 64;
    if (i0 >= P || j0 >= P) return;   // uniform per block

    __shared__ float As[16][64];      // [k][row]
    __shared__ float Bs[16][64];

    int tid = threadIdx.x;
    int tx = tid & 15, ty = tid >> 4;

    float acc[4][4];
    #pragma unroll
    for (int a = 0; a < 4; a++)
        #pragma unroll
        for (int b = 0; b < 4; b++) acc[a][b] = 0.f;

    int lrow = tid >> 2;              // 0..63
    int lk4  = (tid & 3) * 4;         // 0,4,8,12

    for (int k0 = 0; k0 < LL; k0 += 16) {
        float4 av, bv;
        int ai = i0 + lrow;
        int aj = j0 + lrow;
        av = (ai < P) ? *(const float4*)(E + ai*LL + k0 + lk4) : make_float4(0,0,0,0);
        bv = (aj < P) ? *(const float4*)(E + aj*LL + k0 + lk4) : make_float4(0,0,0,0);
        __syncthreads();
        As[lk4+0][lrow] = av.x; As[lk4+1][lrow] = av.y;
        As[lk4+2][lrow] = av.z; As[lk4+3][lrow] = av.w;
        Bs[lk4+0][lrow] = bv.x; Bs[lk4+1][lrow] = bv.y;
        Bs[lk4+2][lrow] = bv.z; Bs[lk4+3][lrow] = bv.w;
        __syncthreads();
        #pragma unroll
        for (int k = 0; k < 16; k++) {
            float4 a4 = *(const float4*)&As[k][ty*4];
            float4 b4 = *(const float4*)&Bs[k][tx*4];
            float ar[4] = {a4.x, a4.y, a4.z, a4.w};
            float br[4] = {b4.x, b4.y, b4.z, b4.w};
            #pragma unroll
            for (int a = 0; a < 4; a++)
                #pragma unroll
                for (int b = 0; b < 4; b++)
                    acc[a][b] += ar[a] * br[b];
        }
    }

    float lsum = 0.f;
    #pragma unroll
    for (int a = 0; a < 4; a++) {
        int i = i0 + ty*4 + a;
        float sqi = (i < P) ? SQ[i] : 0.f;
        #pragma unroll
        for (int b = 0; b < 4; b++) {
            int j = j0 + tx*4 + b;
            if (i < P && j < P) {
                float d;
                if (i == j) d = 0.f;
                else {
                    float d2 = sqi + SQ[j] - 2.f * acc[a][b];
                    d2 = fmaxf(d2, EPSF);
                    d  = d2 * rsqrtf(d2);
                }
                D[i*CC + j] = d;
                lsum += d;
            }
        }
    }

    __shared__ float red[256];
    red[tid] = lsum;
    __syncthreads();
    #pragma unroll
    for (int s2 = 128; s2; s2 >>= 1) {
        if (tid < s2) red[tid] += red[tid + s2];
        __syncthreads();
    }
    if (tid == 0) {
        float w = (bi == bj) ? 1.f : 2.f;   // off-diag tiles cover both triangles
        atomicAdd(SM, red[0] * w);
    }
}

// ==================== kernel 3: Huber sum over pairs =====================
__global__ void k_huber(float* __restrict__ out) {
    int n   = blockIdx.x;
    int tid = threadIdx.x;  // 256
    int P = g_npos[n];
    if (P <= 1) return;     // !valid -> contributes 0

    float cnt = (float)P * (float)(P - 1);
    float ims = cnt / g_sum_s[n];   // 1 / mean_s
    float imt = cnt / g_sum_t[n];

    const float* Ds = g_Ds + (long long)n*CC*CC;
    const float* Dt = g_Dt + (long long)n*CC*CC;

    int T = (P + 63) >> 6;
    float lsum = 0.f;
    for (int bi = 0; bi < T; bi++) {
        for (int bj = bi; bj < T; bj++) {
            float w = (bi == bj) ? 1.f : 2.f;
            int i0 = bi*64, j0 = bj*64;
            for (int e = tid; e < 4096; e += 256) {
                int i = i0 + (e >> 6), j = j0 + (e & 63);
                if (i < P && j < P) {
                    float ds = Ds[i*CC + j];
                    float dt = Dt[i*CC + j];
                    float diff = ds*ims - dt*imt;
                    float ad = fabsf(diff);
                    float h = (ad < 1.f) ? 0.5f*diff*diff : ad - 0.5f;
                    lsum += w * h;
                }
            }
        }
    }

    __shared__ float red[256];
    red[tid] = lsum;
    __syncthreads();
    #pragma unroll
    for (int s2 = 128; s2; s2 >>= 1) {
        if (tid < s2) red[tid] += red[tid + s2];
        __syncthreads();
    }
    if (tid == 0) atomicAdd(out, red[0] / (float)P);
}

// ============================== launcher =================================
extern "C" void kernel_launch(void* const* d_in, const int* in_sizes, int n_in,
                              void* d_out, int out_size) {
    const float* s    = (const float*)d_in[0];
    const float* t    = (const float*)d_in[1];
    const int*   targ = (const int*)d_in[2];
    float* out = (float*)d_out;

    k_compact<<<NB, 512>>>(s, t, targ, out);
    dim3 g2(NPAIR, 2, NB);
    k_dist<<<g2, 256>>>();
    k_huber<<<NB, 256>>>(out);
}

// round 5
// speedup vs baseline: 1.8037x; 1.8037x over previous
#include <cuda_runtime.h>

#define NB 64
#define CC 512
#define LL 256
#define EPSF 1e-12f
#define NT (CC/64)            // 8 row tiles of 64
#define NPAIR (NT*(NT+1)/2)   // 36 upper-triangular tile pairs

// -------- scratch (static device globals: allocation-free rule) ----------
__device__ float g_es[NB*CC*LL];     // compacted student rows
__device__ float g_et[NB*CC*LL];     // compacted teacher rows
__device__ float g_sq_s[NB*CC];      // squared norms (compacted)
__device__ float g_sq_t[NB*CC];
__device__ int   g_idx[NB*CC];       // compaction index lists
__device__ int   g_npos[NB];
__device__ float g_sum_s[NB];        // sum of offdiag distances
__device__ float g_sum_t[NB];
__device__ float g_Ds[NB*CC*CC];     // distance matrices (upper tiles valid)
__device__ float g_Dt[NB*CC*CC];

// =================== kernel 0: index lists + init (tiny) ==================
__global__ void k_index(const int* __restrict__ targ, float* __restrict__ out) {
    int n   = blockIdx.x;
    int tid = threadIdx.x;            // 512 threads
    int lane = tid & 31, wid = tid >> 5;
    __shared__ int sh_wsum[16];

    int m = (targ[n*CC + tid] != 0);
    unsigned bal = __ballot_sync(0xffffffffu, m);
    int wpre = __popc(bal & ((1u << lane) - 1u));
    if (lane == 0) sh_wsum[wid] = __popc(bal);
    __syncthreads();
    if (tid == 0) {
        int acc = 0;
        #pragma unroll
        for (int w = 0; w < 16; w++) { int v = sh_wsum[w]; sh_wsum[w] = acc; acc += v; }
        g_npos[n]  = acc;
        g_sum_s[n] = 0.f;
        g_sum_t[n] = 0.f;
        if (n == 0) out[0] = 0.f;     // d_out poisoned; zero before atomics
    }
    __syncthreads();
    if (m) g_idx[n*CC + sh_wsum[wid] + wpre] = tid;
}

// ============ kernel 1: gather-compact (float4) + row norms ===============
// grid (NB, 16), block 256 = 8 warps. One warp per compacted row, strided.
__global__ void k_copy(const float* __restrict__ s, const float* __restrict__ t) {
    int n   = blockIdx.x;
    int P   = g_npos[n];
    int tid = threadIdx.x;
    int lane = tid & 31, wid = tid >> 5;
    int gw = blockIdx.y * 8 + wid;    // 0..127 global warp per batch

    const float* sb = s + (long long)n*CC*LL;
    const float* tb = t + (long long)n*CC*LL;
    float* des = g_es + (long long)n*CC*LL;
    float* det = g_et + (long long)n*CC*LL;

    for (int r = gw; r < P; r += 128) {
        int src = g_idx[n*CC + r];
        const float4* rs = (const float4*)(sb + src*LL);
        const float4* rt = (const float4*)(tb + src*LL);
        float4* drs = (float4*)(des + r*LL);
        float4* drt = (float4*)(det + r*LL);
        float a = 0.f, b = 0.f;
        #pragma unroll
        for (int c = 0; c < 2; c++) {     // 64 float4 per row / 32 lanes
            int e = lane + c*32;
            float4 v = rs[e]; drs[e] = v;
            a += v.x*v.x + v.y*v.y + v.z*v.z + v.w*v.w;
            float4 w = rt[e]; drt[e] = w;
            b += w.x*w.x + w.y*w.y + w.z*w.z + w.w*w.w;
        }
        #pragma unroll
        for (int off = 16; off; off >>= 1) {
            a += __shfl_down_sync(0xffffffffu, a, off);
            b += __shfl_down_sync(0xffffffffu, b, off);
        }
        if (lane == 0) { g_sq_s[n*CC + r] = a; g_sq_t[n*CC + r] = b; }
    }
}

// ============ kernel 2: Gram -> distances (upper tiles) + sums ============
// block = 256 threads, computes a 64x64 tile, 4x4 register micro-tile
__global__ void k_dist() {
    int n     = blockIdx.z;
    int which = blockIdx.y;   // 0 = student, 1 = teacher

    const float* E  = which ? (g_et   + (long long)n*CC*LL) : (g_es   + (long long)n*CC*LL);
    const float* SQ = which ? (g_sq_t + n*CC)               : (g_sq_s + n*CC);
    float*       D  = which ? (g_Dt   + (long long)n*CC*CC) : (g_Ds   + (long long)n*CC*CC);
    float*       SM = which ? (g_sum_t + n)                 : (g_sum_s + n);

    int P = g_npos[n];

    // decode upper-triangular tile pair (bi <= bj)
    int tlin = blockIdx.x, bi = 0, rem = NT;
    while (tlin >= rem) { tlin -= rem; bi++; rem--; }
    int bj = bi + tlin;
    int i0 = bi * 64, j0 = bj * 64;
    if (i0 >= P || j0 >= P) return;   // uniform per block

    __shared__ float As[16][64];      // [k][row]
    __shared__ float Bs[16][64];

    int tid = threadIdx.x;
    int tx = tid & 15, ty = tid >> 4;

    float acc[4][4];
    #pragma unroll
    for (int a = 0; a < 4; a++)
        #pragma unroll
        for (int b = 0; b < 4; b++) acc[a][b] = 0.f;

    int lrow = tid >> 2;              // 0..63
    int lk4  = (tid & 3) * 4;         // 0,4,8,12

    for (int k0 = 0; k0 < LL; k0 += 16) {
        float4 av, bv;
        int ai = i0 + lrow;
        int aj = j0 + lrow;
        av = (ai < P) ? *(const float4*)(E + ai*LL + k0 + lk4) : make_float4(0,0,0,0);
        bv = (aj < P) ? *(const float4*)(E + aj*LL + k0 + lk4) : make_float4(0,0,0,0);
        __syncthreads();
        As[lk4+0][lrow] = av.x; As[lk4+1][lrow] = av.y;
        As[lk4+2][lrow] = av.z; As[lk4+3][lrow] = av.w;
        Bs[lk4+0][lrow] = bv.x; Bs[lk4+1][lrow] = bv.y;
        Bs[lk4+2][lrow] = bv.z; Bs[lk4+3][lrow] = bv.w;
        __syncthreads();
        #pragma unroll
        for (int k = 0; k < 16; k++) {
            float4 a4 = *(const float4*)&As[k][ty*4];
            float4 b4 = *(const float4*)&Bs[k][tx*4];
            float ar[4] = {a4.x, a4.y, a4.z, a4.w};
            float br[4] = {b4.x, b4.y, b4.z, b4.w};
            #pragma unroll
            for (int a = 0; a < 4; a++)
                #pragma unroll
                for (int b = 0; b < 4; b++)
                    acc[a][b] += ar[a] * br[b];
        }
    }

    float lsum = 0.f;
    #pragma unroll
    for (int a = 0; a < 4; a++) {
        int i = i0 + ty*4 + a;
        float sqi = (i < P) ? SQ[i] : 0.f;
        #pragma unroll
        for (int b = 0; b < 4; b++) {
            int j = j0 + tx*4 + b;
            if (i < P && j < P) {
                float d;
                if (i == j) d = 0.f;
                else {
                    float d2 = sqi + SQ[j] - 2.f * acc[a][b];
                    d2 = fmaxf(d2, EPSF);
                    d  = d2 * rsqrtf(d2);
                }
                D[i*CC + j] = d;
                lsum += d;
            }
        }
    }

    __shared__ float red[256];
    red[tid] = lsum;
    __syncthreads();
    #pragma unroll
    for (int s2 = 128; s2; s2 >>= 1) {
        if (tid < s2) red[tid] += red[tid + s2];
        __syncthreads();
    }
    if (tid == 0) {
        float w = (bi == bj) ? 1.f : 2.f;   // off-diag tiles cover both triangles
        atomicAdd(SM, red[0] * w);
    }
}

// ==================== kernel 3: Huber sum over pairs =====================
// grid (NB, NPAIR), block 256 — one 64x64 tile per block
__global__ void k_huber(float* __restrict__ out) {
    int n   = blockIdx.x;
    int tid = threadIdx.x;
    int P = g_npos[n];
    if (P <= 1) return;     // !valid -> contributes 0

    // decode upper-triangular tile pair (bi <= bj)
    int tlin = blockIdx.y, bi = 0, rem = NT;
    while (tlin >= rem) { tlin -= rem; bi++; rem--; }
    int bj = bi + tlin;
    int i0 = bi * 64, j0 = bj * 64;
    if (i0 >= P || j0 >= P) return;

    float cnt = (float)P * (float)(P - 1);
    float ims = cnt / g_sum_s[n];   // 1 / mean_s
    float imt = cnt / g_sum_t[n];

    const float* Ds = g_Ds + (long long)n*CC*CC;
    const float* Dt = g_Dt + (long long)n*CC*CC;

    float lsum = 0.f;
    for (int e = tid; e < 4096; e += 256) {
        int i = i0 + (e >> 6), j = j0 + (e & 63);
        if (i < P && j < P) {
            float ds = Ds[i*CC + j];
            float dt = Dt[i*CC + j];
            float diff = ds*ims - dt*imt;
            float ad = fabsf(diff);
            float h = (ad < 1.f) ? 0.5f*diff*diff : ad - 0.5f;
            lsum += h;
        }
    }

    __shared__ float red[256];
    red[tid] = lsum;
    __syncthreads();
    #pragma unroll
    for (int s2 = 128; s2; s2 >>= 1) {
        if (tid < s2) red[tid] += red[tid + s2];
        __syncthreads();
    }
    if (tid == 0) {
        float w = (bi == bj) ? 1.f : 2.f;
        atomicAdd(out, red[0] * w / (float)P);
    }
}

// ============================== launcher =================================
extern "C" void kernel_launch(void* const* d_in, const int* in_sizes, int n_in,
                              void* d_out, int out_size) {
    const float* s    = (const float*)d_in[0];
    const float* t    = (const float*)d_in[1];
    const int*   targ = (const int*)d_in[2];
    float* out = (float*)d_out;

    k_index<<<NB, 512>>>(targ, out);
    dim3 g1(NB, 16);
    k_copy<<<g1, 256>>>(s, t);
    dim3 g2(NPAIR, 2, NB);
    k_dist<<<g2, 256>>>();
    dim3 g3(NB, NPAIR);
    k_huber<<<g3, 256>>>(out);
}